// round 1
// baseline (speedup 1.0000x reference)
#include <cuda_runtime.h>
#include <math.h>

#define NE 42
#define NM 8
#define LL 1024
#define DD 768
#define HH 12
#define KK 97
#define FF 256
#define RR 256
#define BBS 4
#define NP 512   /* bs * P */

// ---------------- scratch (device globals; no allocs) ----------------
__device__ float g_emb [BBS*NE*NM*DD];     // mention embeddings (masked)
__device__ float g_as  [BBS*NE*HH*LL];     // entity_as
__device__ float g_t1  [BBS*NE*NM*RR];     // tanh(emb@Wattn+b)
__device__ float g_w   [BBS*NE*KK*NM];     // softmax weights, layout [be][k][m]
__device__ float g_Th  [BBS*NE*NM*DD];     // emb @ Whead_top
__device__ float g_Tt  [BBS*NE*NM*DD];     // emb @ Wtail_top
__device__ float g_S3  [BBS*LL*3];         // seq @ Wlin
__device__ float g_x   [BBS*NE*NE*3];      // conv input
__device__ float g_htss[NP*FF];            // relu(conv) at pair positions
__device__ float g_Rh  [NP*DD];            // htss @ Whead_bot + bhead
__device__ float g_Rt  [NP*DD];            // htss @ Wtail_bot + btail
__device__ float g_hs  [NP*KK*DD];         // tanh head reps
__device__ float g_ts  [NP*KK*DD];         // tanh tail reps
__device__ float g_part[6*NP*KK];          // bilinear partials per d-tile

// ---------------- K1: gather emb + entity_as ----------------
__global__ void k_gather(const float* __restrict__ seq, const float* __restrict__ att,
                         const float* __restrict__ mask, const int* __restrict__ mpos)
{
    int be = blockIdx.x;              // 0..167
    int b  = be / NE;
    int tid = threadIdx.x;
    __shared__ int   spos[NM];
    __shared__ float smk [NM];
    __shared__ float sinv;
    if (tid < NM) {
        int p = mpos[be*NM + tid] + 1;
        p = max(0, min(p, LL-1));
        spos[tid] = p;
        smk[tid]  = mask[be*NM + tid];
    }
    __syncthreads();
    if (tid == 0) {
        float c = 0.f;
        #pragma unroll
        for (int m = 0; m < NM; m++) c += smk[m];
        sinv = 1.0f / fmaxf(c, 1.0f);
    }
    __syncthreads();
    // emb[b,e,m,:] = seq[b,pos,:] * mask
    for (int idx = tid; idx < NM*DD; idx += blockDim.x) {
        int m = idx / DD, d = idx - m*DD;
        g_emb[be*NM*DD + idx] = seq[(b*LL + spos[m])*DD + d] * smk[m];
    }
    // entity_as[b,e,h,l] = sum_m att[b,h,pos_m,l]*mask_m / cnt
    for (int idx = tid; idx < HH*LL; idx += blockDim.x) {
        int h = idx / LL, l = idx - h*LL;
        float acc = 0.f;
        #pragma unroll
        for (int m = 0; m < NM; m++)
            acc += att[((b*HH + h)*LL + spos[m])*LL + l] * smk[m];
        g_as[be*HH*LL + idx] = acc * sinv;
    }
}

// ---------------- generic tiled SGEMM (64x64x16, 256 thr, 4x4/thread) ----------------
// C[M,N] = act(A[M,Kd] @ B[Kd,N] + bias). M%64==0, N%64==0, Kd%16==0, lda/ldb %4==0.
__global__ __launch_bounds__(256) void sgemm64(const float* __restrict__ A, int lda,
                                               const float* __restrict__ B, int ldb,
                                               const float* __restrict__ bias,
                                               float* __restrict__ C, int ldc,
                                               int Kd, int act)
{
    __shared__ float As[16][64];
    __shared__ float Bs[16][68];
    int m0 = blockIdx.y * 64, n0 = blockIdx.x * 64;
    int tid = threadIdx.x;
    int ty = tid >> 4, tx = tid & 15;
    float acc[4][4];
    #pragma unroll
    for (int i = 0; i < 4; i++)
        #pragma unroll
        for (int j = 0; j < 4; j++) acc[i][j] = 0.f;

    for (int k0 = 0; k0 < Kd; k0 += 16) {
        {
            int r  = tid >> 2;
            int kq = (tid & 3) << 2;
            float4 va = *(const float4*)(A + (long)(m0 + r)*lda + k0 + kq);
            As[kq+0][r] = va.x; As[kq+1][r] = va.y; As[kq+2][r] = va.z; As[kq+3][r] = va.w;
            int kb = tid >> 4;
            int cb = (tid & 15) << 2;
            float4 vb = *(const float4*)(B + (long)(k0 + kb)*ldb + n0 + cb);
            *(float4*)&Bs[kb][cb] = vb;
        }
        __syncthreads();
        #pragma unroll
        for (int kk = 0; kk < 16; kk++) {
            float a[4], bv[4];
            #pragma unroll
            for (int i = 0; i < 4; i++) a[i]  = As[kk][ty*4 + i];
            #pragma unroll
            for (int j = 0; j < 4; j++) bv[j] = Bs[kk][tx*4 + j];
            #pragma unroll
            for (int i = 0; i < 4; i++)
                #pragma unroll
                for (int j = 0; j < 4; j++) acc[i][j] += a[i]*bv[j];
        }
        __syncthreads();
    }
    #pragma unroll
    for (int i = 0; i < 4; i++) {
        int row = m0 + ty*4 + i;
        #pragma unroll
        for (int j = 0; j < 4; j++) {
            int col = n0 + tx*4 + j;
            float v = acc[i][j];
            if (bias) v += bias[col];
            if (act)  v = tanhf(v);
            C[(long)row*ldc + col] = v;
        }
    }
}

// ---------------- K3: scores + softmax over mentions ----------------
__global__ void k_scores(const float* __restrict__ attn_net, const float* __restrict__ mask)
{
    int be = blockIdx.x;
    int tid = threadIdx.x;           // 128
    __shared__ float st[NM*RR];
    __shared__ float sneg[NM];
    for (int i = tid; i < NM*RR; i += 128) st[i] = g_t1[be*NM*RR + i];
    if (tid < NM) sneg[tid] = (1.0f - mask[be*NM + tid]) * (-1e6f);
    __syncthreads();
    for (int k = tid; k < KK; k += 128) {
        float sc[NM];
        #pragma unroll
        for (int m = 0; m < NM; m++) sc[m] = sneg[m];
        const float* an = attn_net + k*RR;
        for (int j = 0; j < RR; j++) {
            float av = an[j];
            #pragma unroll
            for (int m = 0; m < NM; m++) sc[m] += st[m*RR + j] * av;
        }
        float mx = sc[0];
        #pragma unroll
        for (int m = 1; m < NM; m++) mx = fmaxf(mx, sc[m]);
        float ssum = 0.f;
        #pragma unroll
        for (int m = 0; m < NM; m++) { sc[m] = expf(sc[m] - mx); ssum += sc[m]; }
        float inv = 1.0f / ssum;
        #pragma unroll
        for (int m = 0; m < NM; m++) g_w[(be*KK + k)*NM + m] = sc[m]*inv;
    }
}

// ---------------- K6: S3 = seq @ Wlin ----------------
__global__ void k_S3(const float* __restrict__ seq, const float* __restrict__ Wlin)
{
    int row = blockIdx.x;            // b*1024 + l
    int tid = threadIdx.x;           // 128
    const float* s = seq + (long)row*DD;
    float a0 = 0.f, a1 = 0.f, a2 = 0.f;
    for (int j = tid; j < DD; j += 128) {
        float v = s[j];
        a0 += v*Wlin[j*3+0]; a1 += v*Wlin[j*3+1]; a2 += v*Wlin[j*3+2];
    }
    __shared__ float red[3][128];
    red[0][tid] = a0; red[1][tid] = a1; red[2][tid] = a2;
    __syncthreads();
    for (int s2 = 64; s2 > 0; s2 >>= 1) {
        if (tid < s2) {
            red[0][tid] += red[0][tid+s2];
            red[1][tid] += red[1][tid+s2];
            red[2][tid] += red[2][tid+s2];
        }
        __syncthreads();
    }
    if (tid < 3) g_S3[row*3 + tid] = red[tid][0];
}

// ---------------- K7: ht (symmetric) + normalization + x = ht@S3 + blin ----------------
__global__ void k_htx(const float* __restrict__ blin)
{
    int b = blockIdx.y;
    int i = blockIdx.x / NE, j = blockIdx.x % NE;
    if (j < i) return;
    int tid = threadIdx.x;           // 256
    const float* ai = g_as + (b*NE + i)*HH*LL;
    const float* aj = g_as + (b*NE + j)*HH*LL;
    const float* s3 = g_S3 + b*LL*3;
    float sum = 0.f, x0 = 0.f, x1 = 0.f, x2 = 0.f;
    for (int l = tid; l < LL; l += 256) {
        float acc = 0.f;
        #pragma unroll
        for (int h = 0; h < HH; h++) acc += ai[h*LL + l] * aj[h*LL + l];
        acc *= (1.0f / HH);
        sum += acc;
        x0 += acc * s3[l*3+0];
        x1 += acc * s3[l*3+1];
        x2 += acc * s3[l*3+2];
    }
    __shared__ float red[4][256];
    red[0][tid] = sum; red[1][tid] = x0; red[2][tid] = x1; red[3][tid] = x2;
    __syncthreads();
    for (int s2 = 128; s2 > 0; s2 >>= 1) {
        if (tid < s2) {
            red[0][tid] += red[0][tid+s2];
            red[1][tid] += red[1][tid+s2];
            red[2][tid] += red[2][tid+s2];
            red[3][tid] += red[3][tid+s2];
        }
        __syncthreads();
    }
    if (tid == 0) {
        float inv = 1.0f / (red[0][0] + 1e-5f);
        float v0 = red[1][0]*inv + blin[0];
        float v1 = red[2][0]*inv + blin[1];
        float v2 = red[3][0]*inv + blin[2];
        float* xo = g_x + ((b*NE + i)*NE + j)*3;
        xo[0] = v0; xo[1] = v1; xo[2] = v2;
        float* xm = g_x + ((b*NE + j)*NE + i)*3;
        xm[0] = v0; xm[1] = v1; xm[2] = v2;
    }
}

// ---------------- K8: 3x3 conv + relu at pair positions only ----------------
__global__ void k_htss(const int* __restrict__ pairs, const float* __restrict__ Wseg,
                       const float* __restrict__ bseg)
{
    int n = blockIdx.x;              // 0..511
    int b = n >> 7;
    int tid = threadIdx.x;           // 256
    __shared__ int shi, sti;
    __shared__ float sx[27];
    if (tid == 0) { shi = pairs[n*2]; sti = pairs[n*2+1]; }
    __syncthreads();
    if (tid < 27) {
        int dy = tid / 9, dx = (tid / 3) % 3, c = tid % 3;
        int ii = shi + dy - 1, jj = sti + dx - 1;
        sx[tid] = (ii >= 0 && ii < NE && jj >= 0 && jj < NE)
                  ? g_x[((b*NE + ii)*NE + jj)*3 + c] : 0.f;
    }
    __syncthreads();
    float acc = bseg[tid];
    #pragma unroll
    for (int t = 0; t < 27; t++) acc += sx[t] * Wseg[t*FF + tid];
    g_htss[n*FF + tid] = fmaxf(acc, 0.f);
}

// ---------------- K10: hs/ts = tanh(sum_m w*T + R) ----------------
__global__ __launch_bounds__(256) void k_hsts(const int* __restrict__ pairs)
{
    int n = blockIdx.x;              // 0..511
    int b = n >> 7;
    int tid = threadIdx.x;           // 256
    __shared__ float sT[2*NM*DD];    // 48KB exactly
    int hi = pairs[n*2], ti = pairs[n*2+1];
    const float* Th = g_Th + (b*NE + hi)*NM*DD;
    const float* Tt = g_Tt + (b*NE + ti)*NM*DD;
    for (int idx = tid; idx < NM*DD; idx += 256) {
        sT[idx]         = Th[idx];
        sT[NM*DD + idx] = Tt[idx];
    }
    float rh[3], rt[3];
    #pragma unroll
    for (int i2 = 0; i2 < 3; i2++) {
        rh[i2] = g_Rh[n*DD + tid + i2*256];
        rt[i2] = g_Rt[n*DD + tid + i2*256];
    }
    __syncthreads();
    const float* wh = g_w + (b*NE + hi)*KK*NM;
    const float* wt = g_w + (b*NE + ti)*KK*NM;
    for (int k = 0; k < KK; k++) {
        float whr[NM], wtr[NM];
        #pragma unroll
        for (int m = 0; m < NM; m++) {
            whr[m] = __ldg(&wh[k*NM + m]);
            wtr[m] = __ldg(&wt[k*NM + m]);
        }
        #pragma unroll
        for (int i2 = 0; i2 < 3; i2++) {
            int d = tid + i2*256;
            float ah = rh[i2], at2 = rt[i2];
            #pragma unroll
            for (int m = 0; m < NM; m++) {
                ah  += whr[m] * sT[m*DD + d];
                at2 += wtr[m] * sT[NM*DD + m*DD + d];
            }
            g_hs[(n*KK + k)*DD + d] = tanhf(ah);
            g_ts[(n*KK + k)*DD + d] = tanhf(at2);
        }
    }
}

// ---------------- K12: bilinear core: per k, C = ts_k @ B_k^T, logits += rowdot(hs_k, C) ----------------
__global__ __launch_bounds__(256) void k_bilinear(const float* __restrict__ Bw)
{
    const int k  = blockIdx.z;
    const int n0 = blockIdx.y * 128;
    const int d0 = blockIdx.x * 128;
    const int tid = threadIdx.x;
    const int ty = tid >> 4, tx = tid & 15;
    __shared__ float As[16][128];
    __shared__ float Bs[16][128];
    __shared__ float red[16][128];
    float acc[8][8];
    #pragma unroll
    for (int i = 0; i < 8; i++)
        #pragma unroll
        for (int j = 0; j < 8; j++) acc[i][j] = 0.f;

    const int SN = KK*DD;                          // ts row stride
    const float* Ab = g_ts + n0*SN + k*DD;         // A[r][p] = Ab[r*SN + p]
    const float* Bb = Bw + (long)k*DD*DD + (long)d0*DD; // B[r][p] = Bb[r*DD + p]

    for (int p0 = 0; p0 < DD; p0 += 16) {
        #pragma unroll
        for (int u = 0; u < 2; u++) {
            int idx = tid + u*256;
            int r = idx >> 2;
            int pq = (idx & 3) << 2;
            float4 va = *(const float4*)(Ab + r*SN + p0 + pq);
            As[pq+0][r] = va.x; As[pq+1][r] = va.y; As[pq+2][r] = va.z; As[pq+3][r] = va.w;
            float4 vb = *(const float4*)(Bb + r*DD + p0 + pq);
            Bs[pq+0][r] = vb.x; Bs[pq+1][r] = vb.y; Bs[pq+2][r] = vb.z; Bs[pq+3][r] = vb.w;
        }
        __syncthreads();
        #pragma unroll
        for (int kk = 0; kk < 16; kk++) {
            float a[8], bv[8];
            #pragma unroll
            for (int i = 0; i < 8; i++) a[i]  = As[kk][ty*8 + i];
            #pragma unroll
            for (int j = 0; j < 8; j++) bv[j] = Bs[kk][tx*8 + j];
            #pragma unroll
            for (int i = 0; i < 8; i++)
                #pragma unroll
                for (int j = 0; j < 8; j++) acc[i][j] += a[i]*bv[j];
        }
        __syncthreads();
    }
    // epilogue: multiply by hs tile, reduce over d within block (deterministic tree)
    #pragma unroll
    for (int i = 0; i < 8; i++) {
        int n = n0 + ty*8 + i;
        const float* hrow = g_hs + (n*KK + k)*DD + d0 + tx*8;
        float pz = 0.f;
        #pragma unroll
        for (int j = 0; j < 8; j++) pz += acc[i][j] * hrow[j];
        red[tx][ty*8 + i] = pz;
    }
    __syncthreads();
    if (tid < 128) {
        float s = 0.f;
        #pragma unroll
        for (int t = 0; t < 16; t++) s += red[t][tid];
        g_part[blockIdx.x*(NP*KK) + (n0 + tid)*KK + k] = s;
    }
}

// ---------------- K13: finalize ----------------
__global__ void k_final(const float* __restrict__ bilb, float* __restrict__ out)
{
    int idx = blockIdx.x*256 + threadIdx.x;
    if (idx >= NP*KK) return;
    int k = idx % KK;
    float s = bilb[k];
    #pragma unroll
    for (int t = 0; t < 6; t++) s += g_part[t*(NP*KK) + idx];
    out[idx] = s;
}

// ---------------- launch ----------------
extern "C" void kernel_launch(void* const* d_in, const int* in_sizes, int n_in,
                              void* d_out, int out_size)
{
    const float* seq      = (const float*)d_in[0];
    const float* att      = (const float*)d_in[1];
    const float* mask     = (const float*)d_in[2];
    const int*   mpos     = (const int*)  d_in[3];
    const int*   pairs    = (const int*)  d_in[4];
    const float* Wattn    = (const float*)d_in[5];
    const float* battn    = (const float*)d_in[6];
    const float* attn_net = (const float*)d_in[7];
    const float* Wlin     = (const float*)d_in[8];
    const float* blin     = (const float*)d_in[9];
    const float* Wseg     = (const float*)d_in[10];
    const float* bseg     = (const float*)d_in[11];
    const float* Whead    = (const float*)d_in[12];
    const float* bhead    = (const float*)d_in[13];
    const float* Wtail    = (const float*)d_in[14];
    const float* btail    = (const float*)d_in[15];
    const float* bil      = (const float*)d_in[16];
    const float* bilb     = (const float*)d_in[17];
    float* out = (float*)d_out;

    float *emb, *t1, *htss, *Th, *Tt, *Rh, *Rt;
    cudaGetSymbolAddress((void**)&emb,  g_emb);
    cudaGetSymbolAddress((void**)&t1,   g_t1);
    cudaGetSymbolAddress((void**)&htss, g_htss);
    cudaGetSymbolAddress((void**)&Th,   g_Th);
    cudaGetSymbolAddress((void**)&Tt,   g_Tt);
    cudaGetSymbolAddress((void**)&Rh,   g_Rh);
    cudaGetSymbolAddress((void**)&Rt,   g_Rt);

    // 1. gather mention embeddings + entity attention rows
    k_gather<<<BBS*NE, 256>>>(seq, att, mask, mpos);
    // 2. t1 = tanh(emb @ Wattn + battn)   [1344,256]
    sgemm64<<<dim3(RR/64, (BBS*NE*NM)/64), 256>>>(emb, DD, Wattn, RR, battn, t1, RR, DD, 1);
    // 3. scores -> softmax weights w
    k_scores<<<BBS*NE, 128>>>(attn_net, mask);
    // 4/5. T_h = emb @ Whead_top, T_t = emb @ Wtail_top   [1344,768]
    sgemm64<<<dim3(DD/64, (BBS*NE*NM)/64), 256>>>(emb, DD, Whead, DD, nullptr, Th, DD, DD, 0);
    sgemm64<<<dim3(DD/64, (BBS*NE*NM)/64), 256>>>(emb, DD, Wtail, DD, nullptr, Tt, DD, DD, 0);
    // 6. S3 = seq @ Wlin  [4096,3]
    k_S3<<<BBS*LL, 128>>>(seq, Wlin);
    // 7. ht (normalized, fused) -> x   [4,42,42,3]
    k_htx<<<dim3(NE*NE, BBS), 256>>>(blin);
    // 8. conv3x3 + relu at pair positions -> htss [512,256]
    k_htss<<<NP, 256>>>(pairs, Wseg, bseg);
    // 9. Rh = htss @ Whead_bot + bhead; Rt likewise   [512,768]
    sgemm64<<<dim3(DD/64, NP/64), 256>>>(htss, FF, Whead + DD*DD, DD, bhead, Rh, DD, FF, 0);
    sgemm64<<<dim3(DD/64, NP/64), 256>>>(htss, FF, Wtail + DD*DD, DD, btail, Rt, DD, FF, 0);
    // 10. hs/ts = tanh(sum_m w*T + R)   [512,97,768]
    k_hsts<<<NP, 256>>>(pairs);
    // 11. bilinear: 97 x (512x768x768) NT-GEMM + row-dot, partials per d-tile
    k_bilinear<<<dim3(DD/128, NP/128, KK), 256>>>(bil);
    // 12. finalize logits = bias + sum partials
    k_final<<<(NP*KK + 255)/256, 256>>>(bilb, out);
}

// round 3
// speedup vs baseline: 1.8645x; 1.8645x over previous
#include <cuda_runtime.h>
#include <cuda_bf16.h>
#include <math.h>
#include <stdint.h>

#define NE 42
#define NM 8
#define LL 1024
#define DD 768
#define HH 12
#define KK 97
#define FF 256
#define RR 256
#define BBS 4
#define NP 512   /* bs * P */

// ---------------- scratch (device globals; no allocs) ----------------
__device__ float g_emb [BBS*NE*NM*DD];
__device__ float g_as  [BBS*NE*HH*LL];
__device__ float g_t1  [BBS*NE*NM*RR];
__device__ float g_w   [BBS*NE*KK*NM];
__device__ float g_Th  [BBS*NE*NM*DD];
__device__ float g_Tt  [BBS*NE*NM*DD];
__device__ float g_S3  [BBS*LL*3];
__device__ float g_x   [BBS*NE*NE*3];
__device__ float g_htss[NP*FF];
__device__ float g_Rh  [NP*DD];
__device__ float g_Rt  [NP*DD];
__device__ float g_hs  [NP*KK*DD];                         // fp32 head reps (epilogue side)
__device__ __align__(16) __nv_bfloat16 g_tshi[NP*KK*DD];   // bf16 split of tail reps
__device__ __align__(16) __nv_bfloat16 g_tslo[NP*KK*DD];
__device__ __align__(16) __nv_bfloat16 g_Bhi [KK*DD*DD];   // bf16 split of bilinear weights
__device__ __align__(16) __nv_bfloat16 g_Blo [KK*DD*DD];
__device__ float g_part[6*NP*KK];

__device__ __forceinline__ float ftanh(float x)
{
    float e = __expf(2.0f * x);
    return 1.0f - 2.0f / (e + 1.0f);
}

// ---------------- K1: gather emb + entity_as ----------------
__global__ void k_gather(const float* __restrict__ seq, const float* __restrict__ att,
                         const float* __restrict__ mask, const int* __restrict__ mpos)
{
    int be = blockIdx.x;
    int b  = be / NE;
    int tid = threadIdx.x;
    __shared__ int   spos[NM];
    __shared__ float smk [NM];
    __shared__ float sinv;
    if (tid < NM) {
        int p = mpos[be*NM + tid] + 1;
        p = max(0, min(p, LL-1));
        spos[tid] = p;
        smk[tid]  = mask[be*NM + tid];
    }
    __syncthreads();
    if (tid == 0) {
        float c = 0.f;
        #pragma unroll
        for (int m = 0; m < NM; m++) c += smk[m];
        sinv = 1.0f / fmaxf(c, 1.0f);
    }
    __syncthreads();
    for (int idx = tid; idx < NM*DD; idx += blockDim.x) {
        int m = idx / DD, d = idx - m*DD;
        g_emb[be*NM*DD + idx] = seq[(b*LL + spos[m])*DD + d] * smk[m];
    }
    for (int idx = tid; idx < HH*LL; idx += blockDim.x) {
        int h = idx / LL, l = idx - h*LL;
        float acc = 0.f;
        #pragma unroll
        for (int m = 0; m < NM; m++)
            acc += att[((b*HH + h)*LL + spos[m])*LL + l] * smk[m];
        g_as[be*HH*LL + idx] = acc * sinv;
    }
}

// ---------------- generic tiled SGEMM (64x64x16) ----------------
__global__ __launch_bounds__(256) void sgemm64(const float* __restrict__ A, int lda,
                                               const float* __restrict__ B, int ldb,
                                               const float* __restrict__ bias,
                                               float* __restrict__ C, int ldc,
                                               int Kd, int act)
{
    __shared__ float As[16][64];
    __shared__ float Bs[16][68];
    int m0 = blockIdx.y * 64, n0 = blockIdx.x * 64;
    int tid = threadIdx.x;
    int ty = tid >> 4, tx = tid & 15;
    float acc[4][4];
    #pragma unroll
    for (int i = 0; i < 4; i++)
        #pragma unroll
        for (int j = 0; j < 4; j++) acc[i][j] = 0.f;

    for (int k0 = 0; k0 < Kd; k0 += 16) {
        {
            int r  = tid >> 2;
            int kq = (tid & 3) << 2;
            float4 va = *(const float4*)(A + (long)(m0 + r)*lda + k0 + kq);
            As[kq+0][r] = va.x; As[kq+1][r] = va.y; As[kq+2][r] = va.z; As[kq+3][r] = va.w;
            int kb = tid >> 4;
            int cb = (tid & 15) << 2;
            float4 vb = *(const float4*)(B + (long)(k0 + kb)*ldb + n0 + cb);
            *(float4*)&Bs[kb][cb] = vb;
        }
        __syncthreads();
        #pragma unroll
        for (int kk = 0; kk < 16; kk++) {
            float a[4], bv[4];
            #pragma unroll
            for (int i = 0; i < 4; i++) a[i]  = As[kk][ty*4 + i];
            #pragma unroll
            for (int j = 0; j < 4; j++) bv[j] = Bs[kk][tx*4 + j];
            #pragma unroll
            for (int i = 0; i < 4; i++)
                #pragma unroll
                for (int j = 0; j < 4; j++) acc[i][j] += a[i]*bv[j];
        }
        __syncthreads();
    }
    #pragma unroll
    for (int i = 0; i < 4; i++) {
        int row = m0 + ty*4 + i;
        #pragma unroll
        for (int j = 0; j < 4; j++) {
            int col = n0 + tx*4 + j;
            float v = acc[i][j];
            if (bias) v += bias[col];
            if (act)  v = ftanh(v);
            C[(long)row*ldc + col] = v;
        }
    }
}

// ---------------- K3: scores + softmax over mentions ----------------
__global__ void k_scores(const float* __restrict__ attn_net, const float* __restrict__ mask)
{
    int be = blockIdx.x;
    int tid = threadIdx.x;
    __shared__ float st[NM*RR];
    __shared__ float sneg[NM];
    for (int i = tid; i < NM*RR; i += 128) st[i] = g_t1[be*NM*RR + i];
    if (tid < NM) sneg[tid] = (1.0f - mask[be*NM + tid]) * (-1e6f);
    __syncthreads();
    for (int k = tid; k < KK; k += 128) {
        float sc[NM];
        #pragma unroll
        for (int m = 0; m < NM; m++) sc[m] = sneg[m];
        const float* an = attn_net + k*RR;
        for (int j = 0; j < RR; j++) {
            float av = an[j];
            #pragma unroll
            for (int m = 0; m < NM; m++) sc[m] += st[m*RR + j] * av;
        }
        float mx = sc[0];
        #pragma unroll
        for (int m = 1; m < NM; m++) mx = fmaxf(mx, sc[m]);
        float ssum = 0.f;
        #pragma unroll
        for (int m = 0; m < NM; m++) { sc[m] = expf(sc[m] - mx); ssum += sc[m]; }
        float inv = 1.0f / ssum;
        #pragma unroll
        for (int m = 0; m < NM; m++) g_w[(be*KK + k)*NM + m] = sc[m]*inv;
    }
}

// ---------------- K6: S3 = seq @ Wlin ----------------
__global__ void k_S3(const float* __restrict__ seq, const float* __restrict__ Wlin)
{
    int row = blockIdx.x;
    int tid = threadIdx.x;
    const float* s = seq + (long)row*DD;
    float a0 = 0.f, a1 = 0.f, a2 = 0.f;
    for (int j = tid; j < DD; j += 128) {
        float v = s[j];
        a0 += v*Wlin[j*3+0]; a1 += v*Wlin[j*3+1]; a2 += v*Wlin[j*3+2];
    }
    __shared__ float red[3][128];
    red[0][tid] = a0; red[1][tid] = a1; red[2][tid] = a2;
    __syncthreads();
    for (int s2 = 64; s2 > 0; s2 >>= 1) {
        if (tid < s2) {
            red[0][tid] += red[0][tid+s2];
            red[1][tid] += red[1][tid+s2];
            red[2][tid] += red[2][tid+s2];
        }
        __syncthreads();
    }
    if (tid < 3) g_S3[row*3 + tid] = red[tid][0];
}

// ---------------- K7: ht + normalization + x = ht@S3 + blin ----------------
__global__ void k_htx(const float* __restrict__ blin)
{
    int b = blockIdx.y;
    int i = blockIdx.x / NE, j = blockIdx.x % NE;
    if (j < i) return;
    int tid = threadIdx.x;
    const float* ai = g_as + (b*NE + i)*HH*LL;
    const float* aj = g_as + (b*NE + j)*HH*LL;
    const float* s3 = g_S3 + b*LL*3;
    float sum = 0.f, x0 = 0.f, x1 = 0.f, x2 = 0.f;
    for (int l = tid; l < LL; l += 256) {
        float acc = 0.f;
        #pragma unroll
        for (int h = 0; h < HH; h++) acc += ai[h*LL + l] * aj[h*LL + l];
        acc *= (1.0f / HH);
        sum += acc;
        x0 += acc * s3[l*3+0];
        x1 += acc * s3[l*3+1];
        x2 += acc * s3[l*3+2];
    }
    __shared__ float red[4][256];
    red[0][tid] = sum; red[1][tid] = x0; red[2][tid] = x1; red[3][tid] = x2;
    __syncthreads();
    for (int s2 = 128; s2 > 0; s2 >>= 1) {
        if (tid < s2) {
            red[0][tid] += red[0][tid+s2];
            red[1][tid] += red[1][tid+s2];
            red[2][tid] += red[2][tid+s2];
            red[3][tid] += red[3][tid+s2];
        }
        __syncthreads();
    }
    if (tid == 0) {
        float inv = 1.0f / (red[0][0] + 1e-5f);
        float v0 = red[1][0]*inv + blin[0];
        float v1 = red[2][0]*inv + blin[1];
        float v2 = red[3][0]*inv + blin[2];
        float* xo = g_x + ((b*NE + i)*NE + j)*3;
        xo[0] = v0; xo[1] = v1; xo[2] = v2;
        float* xm = g_x + ((b*NE + j)*NE + i)*3;
        xm[0] = v0; xm[1] = v1; xm[2] = v2;
    }
}

// ---------------- K8: 3x3 conv + relu at pair positions ----------------
__global__ void k_htss(const int* __restrict__ pairs, const float* __restrict__ Wseg,
                       const float* __restrict__ bseg)
{
    int n = blockIdx.x;
    int b = n >> 7;
    int tid = threadIdx.x;
    __shared__ int shi, sti;
    __shared__ float sx[27];
    if (tid == 0) { shi = pairs[n*2]; sti = pairs[n*2+1]; }
    __syncthreads();
    if (tid < 27) {
        int dy = tid / 9, dx = (tid / 3) % 3, c = tid % 3;
        int ii = shi + dy - 1, jj = sti + dx - 1;
        sx[tid] = (ii >= 0 && ii < NE && jj >= 0 && jj < NE)
                  ? g_x[((b*NE + ii)*NE + jj)*3 + c] : 0.f;
    }
    __syncthreads();
    float acc = bseg[tid];
    #pragma unroll
    for (int t = 0; t < 27; t++) acc += sx[t] * Wseg[t*FF + tid];
    g_htss[n*FF + tid] = fmaxf(acc, 0.f);
}

// ---------------- K10: hs fp32 ; ts -> bf16 hi/lo split ----------------
__global__ __launch_bounds__(256) void k_hsts(const int* __restrict__ pairs)
{
    int n = blockIdx.x;
    int b = n >> 7;
    int tid = threadIdx.x;
    __shared__ float sT[2*NM*DD];
    int hi = pairs[n*2], ti = pairs[n*2+1];
    const float* Th = g_Th + (b*NE + hi)*NM*DD;
    const float* Tt = g_Tt + (b*NE + ti)*NM*DD;
    for (int idx = tid; idx < NM*DD; idx += 256) {
        sT[idx]         = Th[idx];
        sT[NM*DD + idx] = Tt[idx];
    }
    float rh[3], rt[3];
    #pragma unroll
    for (int i2 = 0; i2 < 3; i2++) {
        rh[i2] = g_Rh[n*DD + tid + i2*256];
        rt[i2] = g_Rt[n*DD + tid + i2*256];
    }
    __syncthreads();
    const float* wh = g_w + (b*NE + hi)*KK*NM;
    const float* wt = g_w + (b*NE + ti)*KK*NM;
    for (int k = 0; k < KK; k++) {
        float whr[NM], wtr[NM];
        #pragma unroll
        for (int m = 0; m < NM; m++) {
            whr[m] = __ldg(&wh[k*NM + m]);
            wtr[m] = __ldg(&wt[k*NM + m]);
        }
        #pragma unroll
        for (int i2 = 0; i2 < 3; i2++) {
            int d = tid + i2*256;
            float ah = rh[i2], at2 = rt[i2];
            #pragma unroll
            for (int m = 0; m < NM; m++) {
                ah  += whr[m] * sT[m*DD + d];
                at2 += wtr[m] * sT[NM*DD + m*DD + d];
            }
            size_t o = (size_t)(n*KK + k)*DD + d;
            g_hs[o] = ftanh(ah);
            float tv = ftanh(at2);
            __nv_bfloat16 thi = __float2bfloat16(tv);
            g_tshi[o] = thi;
            g_tslo[o] = __float2bfloat16(tv - __bfloat162float(thi));
        }
    }
}

// ---------------- K11: split bilinear weights into bf16 hi/lo ----------------
__global__ void k_bsplit(const float* __restrict__ bil)
{
    size_t i4 = (size_t)blockIdx.x * 256 + threadIdx.x;
    const size_t N4 = (size_t)KK*DD*DD / 4;
    if (i4 >= N4) return;
    float4 v = ((const float4*)bil)[i4];
    __nv_bfloat16 h0 = __float2bfloat16(v.x), h1 = __float2bfloat16(v.y);
    __nv_bfloat16 h2 = __float2bfloat16(v.z), h3 = __float2bfloat16(v.w);
    __nv_bfloat16 l0 = __float2bfloat16(v.x - __bfloat162float(h0));
    __nv_bfloat16 l1 = __float2bfloat16(v.y - __bfloat162float(h1));
    __nv_bfloat16 l2 = __float2bfloat16(v.z - __bfloat162float(h2));
    __nv_bfloat16 l3 = __float2bfloat16(v.w - __bfloat162float(h3));
    __nv_bfloat162* ph = (__nv_bfloat162*)g_Bhi;
    __nv_bfloat162* pl = (__nv_bfloat162*)g_Blo;
    ph[i4*2+0] = __nv_bfloat162(h0, h1);
    ph[i4*2+1] = __nv_bfloat162(h2, h3);
    pl[i4*2+0] = __nv_bfloat162(l0, l1);
    pl[i4*2+1] = __nv_bfloat162(l2, l3);
}

// ================= HMMA (mma.sync bf16) bilinear core =================
// C[n, d] = sum over 3 segments of A_seg[n, p] * B_seg[d, p], then
// logits_part = rowdot(C, hs). Block tile 128x128, Kstage = 64 bf16.
#define SW128(o) ((o) ^ (((o) >> 3) & 0x70))
#define TILE_BYTES 16384                   /* 128 rows x 128B */
#define PIPE_BYTES (4*TILE_BYTES)          /* 2 bufs x (A+B) */
#define SH_PITCH 132
#define SMEM_DYN (128*SH_PITCH*4 + 128*2*4 + 1024)

__device__ __forceinline__ void cp16(uint32_t dst, const void* src)
{
    asm volatile("cp.async.cg.shared.global [%0], [%1], 16;" :: "r"(dst), "l"(src));
}
__device__ __forceinline__ void ldm4(uint32_t* r, uint32_t addr)
{
    asm volatile("ldmatrix.sync.aligned.m8n8.x4.shared.b16 {%0,%1,%2,%3}, [%4];"
                 : "=r"(r[0]), "=r"(r[1]), "=r"(r[2]), "=r"(r[3]) : "r"(addr));
}
__device__ __forceinline__ void mma16816(float* c, const uint32_t* a, const uint32_t* b)
{
    asm volatile("mma.sync.aligned.m16n8k16.row.col.f32.bf16.bf16.f32 "
                 "{%0,%1,%2,%3}, {%4,%5,%6,%7}, {%8,%9}, {%0,%1,%2,%3};"
                 : "+f"(c[0]), "+f"(c[1]), "+f"(c[2]), "+f"(c[3])
                 : "r"(a[0]), "r"(a[1]), "r"(a[2]), "r"(a[3]), "r"(b[0]), "r"(b[1]));
}

__global__ __launch_bounds__(256) void k_bilinear_mma()
{
    extern __shared__ char dsm[];
    char* smem = (char*)((((uintptr_t)dsm) + 1023) & ~(uintptr_t)1023);
    uint32_t sbase = (uint32_t)__cvta_generic_to_shared(smem);

    const int k  = blockIdx.y;
    const int nt = blockIdx.x & 3;
    const int dt = blockIdx.x >> 2;        // 0..5
    const int n0 = nt * 128, d0 = dt * 128;
    const int tid = threadIdx.x;
    const int lane = tid & 31, wid = tid >> 5;
    const int wm = (wid & 3) * 32;         // warp m offset (pairs)
    const int wn = (wid >> 2) * 64;        // warp n offset (d)

    const size_t aoff = ((size_t)n0 * KK + k) * DD;
    const size_t boff = ((size_t)k * DD + d0) * DD;
    const __nv_bfloat16* Aseg[3] = { g_tshi + aoff, g_tslo + aoff, g_tshi + aoff };
    const __nv_bfloat16* Bseg[3] = { g_Bhi  + boff, g_Bhi  + boff, g_Blo  + boff };

    float acc[2][8][4];
    #pragma unroll
    for (int mi = 0; mi < 2; mi++)
        #pragma unroll
        for (int ni = 0; ni < 8; ni++)
            #pragma unroll
            for (int j = 0; j < 4; j++) acc[mi][ni][j] = 0.f;

    // fill stage it into buffer buf: A tile 128x64 bf16 + B tile 128x64 bf16
    auto fill = [&](int it, int buf) {
        int seg = it / 12;
        int k0  = (it % 12) * 64;
        const __nv_bfloat16* As = Aseg[seg];
        const __nv_bfloat16* Bs = Bseg[seg];
        uint32_t abase = sbase + buf*2*TILE_BYTES;
        uint32_t bbase = abase + TILE_BYTES;
        #pragma unroll
        for (int j = 0; j < 8; j++) {
            int c = tid + j*256;           // 0..2047
            if (c < 1024) {
                int r = c >> 3, q = c & 7;
                cp16(abase + SW128(r*128 + q*16), As + (size_t)r*(KK*DD) + k0 + q*8);
            } else {
                int c2 = c - 1024;
                int r = c2 >> 3, q = c2 & 7;
                cp16(bbase + SW128(r*128 + q*16), Bs + (size_t)r*DD + k0 + q*8);
            }
        }
    };

    fill(0, 0);
    asm volatile("cp.async.commit_group;");

    for (int i = 0; i < 36; i++) {
        if (i + 1 < 36) {
            fill(i + 1, (i + 1) & 1);
            asm volatile("cp.async.commit_group;");
            asm volatile("cp.async.wait_group 1;");
        } else {
            asm volatile("cp.async.wait_group 0;");
        }
        __syncthreads();

        uint32_t abase = sbase + (i & 1)*2*TILE_BYTES;
        uint32_t bbase = abase + TILE_BYTES;
        #pragma unroll
        for (int ks = 0; ks < 4; ks++) {
            uint32_t af[2][4];
            #pragma unroll
            for (int mi = 0; mi < 2; mi++) {
                int row = wm + mi*16 + ((lane >> 3) & 1)*8 + (lane & 7);
                int cb  = ks*32 + (lane >> 4)*16;
                ldm4(af[mi], abase + SW128(row*128 + cb));
            }
            uint32_t bf[8][2];
            #pragma unroll
            for (int q = 0; q < 4; q++) {
                uint32_t r[4];
                int nrow = wn + (2*q + (lane >> 4))*8 + (lane & 7);
                int cb   = ks*32 + ((lane >> 3) & 1)*16;
                ldm4(r, bbase + SW128(nrow*128 + cb));
                bf[2*q+0][0] = r[0]; bf[2*q+0][1] = r[1];
                bf[2*q+1][0] = r[2]; bf[2*q+1][1] = r[3];
            }
            #pragma unroll
            for (int mi = 0; mi < 2; mi++)
                #pragma unroll
                for (int ni = 0; ni < 8; ni++)
                    mma16816(acc[mi][ni], af[mi], bf[ni]);
        }
        __syncthreads();
    }

    // ---- epilogue: partial[n] = sum_d C[n][d]*hs[n][d] ----
    float* sH  = (float*)smem;                 // [128][SH_PITCH]
    float* red = (float*)(smem + 128*SH_PITCH*4);  // [128][2]
    for (int idx = tid; idx < 128*32; idx += 256) {
        int r = idx >> 5, c4 = idx & 31;
        float4 v = *(const float4*)(g_hs + ((size_t)(n0 + r)*KK + k)*DD + d0 + c4*4);
        *(float4*)&sH[r*SH_PITCH + c4*4] = v;
    }
    __syncthreads();

    float p[2][2] = {{0.f, 0.f}, {0.f, 0.f}};
    #pragma unroll
    for (int mi = 0; mi < 2; mi++) {
        int r0 = wm + mi*16 + (lane >> 2);
        #pragma unroll
        for (int ni = 0; ni < 8; ni++) {
            int cb = wn + ni*8 + (lane & 3)*2;
            p[mi][0] += acc[mi][ni][0]*sH[r0*SH_PITCH + cb]
                      + acc[mi][ni][1]*sH[r0*SH_PITCH + cb + 1];
            p[mi][1] += acc[mi][ni][2]*sH[(r0+8)*SH_PITCH + cb]
                      + acc[mi][ni][3]*sH[(r0+8)*SH_PITCH + cb + 1];
        }
    }
    #pragma unroll
    for (int mi = 0; mi < 2; mi++)
        #pragma unroll
        for (int h = 0; h < 2; h++) {
            p[mi][h] += __shfl_xor_sync(0xffffffffu, p[mi][h], 1);
            p[mi][h] += __shfl_xor_sync(0xffffffffu, p[mi][h], 2);
        }
    if ((lane & 3) == 0) {
        int nw = wid >> 2;
        int rr = lane >> 2;
        #pragma unroll
        for (int mi = 0; mi < 2; mi++) {
            red[(wm + mi*16 + rr)*2 + nw]     = p[mi][0];
            red[(wm + mi*16 + rr + 8)*2 + nw] = p[mi][1];
        }
    }
    __syncthreads();
    if (tid < 128)
        g_part[((size_t)dt*NP + n0 + tid)*KK + k] = red[tid*2] + red[tid*2+1];
}

// ---------------- K13: finalize ----------------
__global__ void k_final(const float* __restrict__ bilb, float* __restrict__ out)
{
    int idx = blockIdx.x*256 + threadIdx.x;
    if (idx >= NP*KK) return;
    int k = idx % KK;
    float s = bilb[k];
    #pragma unroll
    for (int t = 0; t < 6; t++) s += g_part[t*(NP*KK) + idx];
    out[idx] = s;
}

// ---------------- launch ----------------
extern "C" void kernel_launch(void* const* d_in, const int* in_sizes, int n_in,
                              void* d_out, int out_size)
{
    const float* seq      = (const float*)d_in[0];
    const float* att      = (const float*)d_in[1];
    const float* mask     = (const float*)d_in[2];
    const int*   mpos     = (const int*)  d_in[3];
    const int*   pairs    = (const int*)  d_in[4];
    const float* Wattn    = (const float*)d_in[5];
    const float* battn    = (const float*)d_in[6];
    const float* attn_net = (const float*)d_in[7];
    const float* Wlin     = (const float*)d_in[8];
    const float* blin     = (const float*)d_in[9];
    const float* Wseg     = (const float*)d_in[10];
    const float* bseg     = (const float*)d_in[11];
    const float* Whead    = (const float*)d_in[12];
    const float* bhead    = (const float*)d_in[13];
    const float* Wtail    = (const float*)d_in[14];
    const float* btail    = (const float*)d_in[15];
    const float* bil      = (const float*)d_in[16];
    const float* bilb     = (const float*)d_in[17];
    float* out = (float*)d_out;

    float *emb, *t1, *htss, *Th, *Tt, *Rh, *Rt;
    cudaGetSymbolAddress((void**)&emb,  g_emb);
    cudaGetSymbolAddress((void**)&t1,   g_t1);
    cudaGetSymbolAddress((void**)&htss, g_htss);
    cudaGetSymbolAddress((void**)&Th,   g_Th);
    cudaGetSymbolAddress((void**)&Tt,   g_Tt);
    cudaGetSymbolAddress((void**)&Rh,   g_Rh);
    cudaGetSymbolAddress((void**)&Rt,   g_Rt);

    cudaFuncSetAttribute(k_bilinear_mma, cudaFuncAttributeMaxDynamicSharedMemorySize, SMEM_DYN);

    // B weight split (independent; longest prep) first
    {
        size_t n4 = (size_t)KK*DD*DD/4;
        k_bsplit<<<(unsigned)((n4 + 255)/256), 256>>>(bil);
    }
    // 1. gather mention embeddings + entity attention rows
    k_gather<<<BBS*NE, 256>>>(seq, att, mask, mpos);
    // 2. t1 = tanh(emb @ Wattn + battn)
    sgemm64<<<dim3(RR/64, (BBS*NE*NM)/64), 256>>>(emb, DD, Wattn, RR, battn, t1, RR, DD, 1);
    // 3. softmax weights
    k_scores<<<BBS*NE, 128>>>(attn_net, mask);
    // 4/5. T_h / T_t
    sgemm64<<<dim3(DD/64, (BBS*NE*NM)/64), 256>>>(emb, DD, Whead, DD, nullptr, Th, DD, DD, 0);
    sgemm64<<<dim3(DD/64, (BBS*NE*NM)/64), 256>>>(emb, DD, Wtail, DD, nullptr, Tt, DD, DD, 0);
    // 6. S3 = seq @ Wlin
    k_S3<<<BBS*LL, 128>>>(seq, Wlin);
    // 7. ht -> x
    k_htx<<<dim3(NE*NE, BBS), 256>>>(blin);
    // 8. conv + relu at pairs
    k_htss<<<NP, 256>>>(pairs, Wseg, bseg);
    // 9. Rh / Rt
    sgemm64<<<dim3(DD/64, NP/64), 256>>>(htss, FF, Whead + DD*DD, DD, bhead, Rh, DD, FF, 0);
    sgemm64<<<dim3(DD/64, NP/64), 256>>>(htss, FF, Wtail + DD*DD, DD, btail, Rt, DD, FF, 0);
    // 10. hs fp32 + ts bf16 split
    k_hsts<<<NP, 256>>>(pairs);
    // 11. HMMA bilinear: grid (24 tiles, 97 k) so same-k blocks share B via L2
    k_bilinear_mma<<<dim3(24, 97), 256, SMEM_DYN>>>();
    // 12. finalize
    k_final<<<(NP*KK + 255)/256, 256>>>(bilb, out);
}

// round 4
// speedup vs baseline: 2.2962x; 1.2315x over previous
#include <cuda_runtime.h>
#include <cuda_fp16.h>
#include <math.h>
#include <stdint.h>

#define NE 42
#define NM 8
#define LL 1024
#define DD 768
#define HH 12
#define KK 97
#define FF 256
#define RR 256
#define BBS 4
#define NP 512   /* bs * P */

// ---------------- scratch (device globals; no allocs) ----------------
__device__ float g_emb [BBS*NE*NM*DD];
__device__ float g_as  [BBS*NE*HH*LL];
__device__ float g_t1  [BBS*NE*NM*RR];
__device__ float g_anT [RR*128];           // attn_net transposed, padded 97->128
__device__ float g_sc  [BBS*NE*NM*128];    // raw scores [be*m, k]
__device__ float g_w   [BBS*NE*KK*NM];
__device__ float g_Th  [BBS*NE*NM*DD];
__device__ float g_Tt  [BBS*NE*NM*DD];
__device__ float g_S3  [BBS*LL*3];
__device__ float g_x   [BBS*NE*NE*3];
__device__ float g_htss[NP*FF];
__device__ float g_Rh  [NP*DD];
__device__ float g_Rt  [NP*DD];
__device__ float g_hs  [NP*KK*DD];                     // fp32 head reps (epilogue side)
__device__ __align__(16) __half g_tshi[NP*KK*DD];      // fp16 hi of tail reps
__device__ __align__(16) __half g_tslo[NP*KK*DD];      // fp16 lo of tail reps
__device__ __align__(16) __half g_Bhi [KK*DD*DD];      // fp16 of bilinear weights
__device__ float g_part[6*NP*KK];

__device__ __forceinline__ float ftanh(float x)
{
    float e = __expf(2.0f * x);
    return 1.0f - 2.0f / (e + 1.0f);
}

// ---------------- K1: gather emb + entity_as ----------------
__global__ void k_gather(const float* __restrict__ seq, const float* __restrict__ att,
                         const float* __restrict__ mask, const int* __restrict__ mpos)
{
    int be = blockIdx.x;
    int b  = be / NE;
    int tid = threadIdx.x;
    __shared__ int   spos[NM];
    __shared__ float smk [NM];
    __shared__ float sinv;
    if (tid < NM) {
        int p = mpos[be*NM + tid] + 1;
        p = max(0, min(p, LL-1));
        spos[tid] = p;
        smk[tid]  = mask[be*NM + tid];
    }
    __syncthreads();
    if (tid == 0) {
        float c = 0.f;
        #pragma unroll
        for (int m = 0; m < NM; m++) c += smk[m];
        sinv = 1.0f / fmaxf(c, 1.0f);
    }
    __syncthreads();
    for (int idx = tid; idx < NM*DD; idx += blockDim.x) {
        int m = idx / DD, d = idx - m*DD;
        g_emb[be*NM*DD + idx] = seq[(b*LL + spos[m])*DD + d] * smk[m];
    }
    for (int idx = tid; idx < HH*LL; idx += blockDim.x) {
        int h = idx / LL, l = idx - h*LL;
        float acc = 0.f;
        #pragma unroll
        for (int m = 0; m < NM; m++)
            acc += att[((b*HH + h)*LL + spos[m])*LL + l] * smk[m];
        g_as[be*HH*LL + idx] = acc * sinv;
    }
}

// ---------------- generic tiled SGEMM (64x64x16) ----------------
__global__ __launch_bounds__(256) void sgemm64(const float* __restrict__ A, int lda,
                                               const float* __restrict__ B, int ldb,
                                               const float* __restrict__ bias,
                                               float* __restrict__ C, int ldc,
                                               int Kd, int act)
{
    __shared__ float As[16][64];
    __shared__ float Bs[16][68];
    int m0 = blockIdx.y * 64, n0 = blockIdx.x * 64;
    int tid = threadIdx.x;
    int ty = tid >> 4, tx = tid & 15;
    float acc[4][4];
    #pragma unroll
    for (int i = 0; i < 4; i++)
        #pragma unroll
        for (int j = 0; j < 4; j++) acc[i][j] = 0.f;

    for (int k0 = 0; k0 < Kd; k0 += 16) {
        {
            int r  = tid >> 2;
            int kq = (tid & 3) << 2;
            float4 va = *(const float4*)(A + (long)(m0 + r)*lda + k0 + kq);
            As[kq+0][r] = va.x; As[kq+1][r] = va.y; As[kq+2][r] = va.z; As[kq+3][r] = va.w;
            int kb = tid >> 4;
            int cb = (tid & 15) << 2;
            float4 vb = *(const float4*)(B + (long)(k0 + kb)*ldb + n0 + cb);
            *(float4*)&Bs[kb][cb] = vb;
        }
        __syncthreads();
        #pragma unroll
        for (int kk = 0; kk < 16; kk++) {
            float a[4], bv[4];
            #pragma unroll
            for (int i = 0; i < 4; i++) a[i]  = As[kk][ty*4 + i];
            #pragma unroll
            for (int j = 0; j < 4; j++) bv[j] = Bs[kk][tx*4 + j];
            #pragma unroll
            for (int i = 0; i < 4; i++)
                #pragma unroll
                for (int j = 0; j < 4; j++) acc[i][j] += a[i]*bv[j];
        }
        __syncthreads();
    }
    #pragma unroll
    for (int i = 0; i < 4; i++) {
        int row = m0 + ty*4 + i;
        #pragma unroll
        for (int j = 0; j < 4; j++) {
            int col = n0 + tx*4 + j;
            float v = acc[i][j];
            if (bias) v += bias[col];
            if (act)  v = ftanh(v);
            C[(long)row*ldc + col] = v;
        }
    }
}

// ---------------- dual-output SGEMM: two B/C pairs, same A ----------------
__global__ __launch_bounds__(256) void sgemm64_dual(const float* __restrict__ A, int lda,
                                                    const float* __restrict__ B0,
                                                    const float* __restrict__ B1, int ldb,
                                                    const float* __restrict__ bias0,
                                                    const float* __restrict__ bias1,
                                                    float* __restrict__ C0,
                                                    float* __restrict__ C1, int ldc,
                                                    int Kd)
{
    __shared__ float As[16][64];
    __shared__ float Bs[16][68];
    int hx = gridDim.x >> 1;
    int half = blockIdx.x >= hx;
    const float* B    = half ? B1    : B0;
    const float* bias = half ? bias1 : bias0;
    float*       C    = half ? C1    : C0;
    int n0 = (blockIdx.x - half*hx) * 64;
    int m0 = blockIdx.y * 64;
    int tid = threadIdx.x;
    int ty = tid >> 4, tx = tid & 15;
    float acc[4][4];
    #pragma unroll
    for (int i = 0; i < 4; i++)
        #pragma unroll
        for (int j = 0; j < 4; j++) acc[i][j] = 0.f;

    for (int k0 = 0; k0 < Kd; k0 += 16) {
        {
            int r  = tid >> 2;
            int kq = (tid & 3) << 2;
            float4 va = *(const float4*)(A + (long)(m0 + r)*lda + k0 + kq);
            As[kq+0][r] = va.x; As[kq+1][r] = va.y; As[kq+2][r] = va.z; As[kq+3][r] = va.w;
            int kb = tid >> 4;
            int cb = (tid & 15) << 2;
            float4 vb = *(const float4*)(B + (long)(k0 + kb)*ldb + n0 + cb);
            *(float4*)&Bs[kb][cb] = vb;
        }
        __syncthreads();
        #pragma unroll
        for (int kk = 0; kk < 16; kk++) {
            float a[4], bv[4];
            #pragma unroll
            for (int i = 0; i < 4; i++) a[i]  = As[kk][ty*4 + i];
            #pragma unroll
            for (int j = 0; j < 4; j++) bv[j] = Bs[kk][tx*4 + j];
            #pragma unroll
            for (int i = 0; i < 4; i++)
                #pragma unroll
                for (int j = 0; j < 4; j++) acc[i][j] += a[i]*bv[j];
        }
        __syncthreads();
    }
    #pragma unroll
    for (int i = 0; i < 4; i++) {
        int row = m0 + ty*4 + i;
        #pragma unroll
        for (int j = 0; j < 4; j++) {
            int col = n0 + tx*4 + j;
            float v = acc[i][j];
            if (bias) v += bias[col];
            C[(long)row*ldc + col] = v;
        }
    }
}

// ---------------- attn_net transpose (97x256 -> 256x128 padded) ----------------
__global__ void k_antr(const float* __restrict__ attn_net)
{
    int idx = blockIdx.x*256 + threadIdx.x;
    if (idx >= RR*128) return;
    int j = idx >> 7, k = idx & 127;
    g_anT[idx] = (k < KK) ? attn_net[k*RR + j] : 0.f;
}

// ---------------- softmax over mentions ----------------
__global__ void k_softmax(const float* __restrict__ mask)
{
    int be = blockIdx.x;
    int k  = threadIdx.x;            // 128 threads, 97 active
    if (k >= KK) return;
    float neg[NM], sc[NM];
    #pragma unroll
    for (int m = 0; m < NM; m++)
        neg[m] = (1.0f - mask[be*NM + m]) * (-1e6f);
    #pragma unroll
    for (int m = 0; m < NM; m++)
        sc[m] = g_sc[((size_t)(be*NM + m))*128 + k] + neg[m];
    float mx = sc[0];
    #pragma unroll
    for (int m = 1; m < NM; m++) mx = fmaxf(mx, sc[m]);
    float ssum = 0.f;
    #pragma unroll
    for (int m = 0; m < NM; m++) { sc[m] = expf(sc[m] - mx); ssum += sc[m]; }
    float inv = 1.0f / ssum;
    #pragma unroll
    for (int m = 0; m < NM; m++) g_w[(be*KK + k)*NM + m] = sc[m]*inv;
}

// ---------------- K6: S3 = seq @ Wlin ----------------
__global__ void k_S3(const float* __restrict__ seq, const float* __restrict__ Wlin)
{
    int row = blockIdx.x;
    int tid = threadIdx.x;
    const float* s = seq + (long)row*DD;
    float a0 = 0.f, a1 = 0.f, a2 = 0.f;
    for (int j = tid; j < DD; j += 128) {
        float v = s[j];
        a0 += v*Wlin[j*3+0]; a1 += v*Wlin[j*3+1]; a2 += v*Wlin[j*3+2];
    }
    __shared__ float red[3][128];
    red[0][tid] = a0; red[1][tid] = a1; red[2][tid] = a2;
    __syncthreads();
    for (int s2 = 64; s2 > 0; s2 >>= 1) {
        if (tid < s2) {
            red[0][tid] += red[0][tid+s2];
            red[1][tid] += red[1][tid+s2];
            red[2][tid] += red[2][tid+s2];
        }
        __syncthreads();
    }
    if (tid < 3) g_S3[row*3 + tid] = red[tid][0];
}

// ---------------- K7: ht + normalization + x = ht@S3 + blin ----------------
__global__ void k_htx(const float* __restrict__ blin)
{
    int b = blockIdx.y;
    int i = blockIdx.x / NE, j = blockIdx.x % NE;
    if (j < i) return;
    int tid = threadIdx.x;
    const float* ai = g_as + (b*NE + i)*HH*LL;
    const float* aj = g_as + (b*NE + j)*HH*LL;
    const float* s3 = g_S3 + b*LL*3;
    float sum = 0.f, x0 = 0.f, x1 = 0.f, x2 = 0.f;
    for (int l = tid; l < LL; l += 256) {
        float acc = 0.f;
        #pragma unroll
        for (int h = 0; h < HH; h++) acc += ai[h*LL + l] * aj[h*LL + l];
        acc *= (1.0f / HH);
        sum += acc;
        x0 += acc * s3[l*3+0];
        x1 += acc * s3[l*3+1];
        x2 += acc * s3[l*3+2];
    }
    __shared__ float red[4][256];
    red[0][tid] = sum; red[1][tid] = x0; red[2][tid] = x1; red[3][tid] = x2;
    __syncthreads();
    for (int s2 = 128; s2 > 0; s2 >>= 1) {
        if (tid < s2) {
            red[0][tid] += red[0][tid+s2];
            red[1][tid] += red[1][tid+s2];
            red[2][tid] += red[2][tid+s2];
            red[3][tid] += red[3][tid+s2];
        }
        __syncthreads();
    }
    if (tid == 0) {
        float inv = 1.0f / (red[0][0] + 1e-5f);
        float v0 = red[1][0]*inv + blin[0];
        float v1 = red[2][0]*inv + blin[1];
        float v2 = red[3][0]*inv + blin[2];
        float* xo = g_x + ((b*NE + i)*NE + j)*3;
        xo[0] = v0; xo[1] = v1; xo[2] = v2;
        float* xm = g_x + ((b*NE + j)*NE + i)*3;
        xm[0] = v0; xm[1] = v1; xm[2] = v2;
    }
}

// ---------------- K8: 3x3 conv + relu at pair positions ----------------
__global__ void k_htss(const int* __restrict__ pairs, const float* __restrict__ Wseg,
                       const float* __restrict__ bseg)
{
    int n = blockIdx.x;
    int b = n >> 7;
    int tid = threadIdx.x;
    __shared__ int shi, sti;
    __shared__ float sx[27];
    if (tid == 0) { shi = pairs[n*2]; sti = pairs[n*2+1]; }
    __syncthreads();
    if (tid < 27) {
        int dy = tid / 9, dx = (tid / 3) % 3, c = tid % 3;
        int ii = shi + dy - 1, jj = sti + dx - 1;
        sx[tid] = (ii >= 0 && ii < NE && jj >= 0 && jj < NE)
                  ? g_x[((b*NE + ii)*NE + jj)*3 + c] : 0.f;
    }
    __syncthreads();
    float acc = bseg[tid];
    #pragma unroll
    for (int t = 0; t < 27; t++) acc += sx[t] * Wseg[t*FF + tid];
    g_htss[n*FF + tid] = fmaxf(acc, 0.f);
}

// ---------------- K10: hs fp32 ; ts -> fp16 hi/lo split ----------------
__global__ __launch_bounds__(256) void k_hsts(const int* __restrict__ pairs)
{
    int n = blockIdx.x;
    int b = n >> 7;
    int tid = threadIdx.x;
    __shared__ float sT[2*NM*DD];
    int hi = pairs[n*2], ti = pairs[n*2+1];
    const float* Th = g_Th + (b*NE + hi)*NM*DD;
    const float* Tt = g_Tt + (b*NE + ti)*NM*DD;
    for (int idx = tid; idx < NM*DD; idx += 256) {
        sT[idx]         = Th[idx];
        sT[NM*DD + idx] = Tt[idx];
    }
    float rh[3], rt[3];
    #pragma unroll
    for (int i2 = 0; i2 < 3; i2++) {
        rh[i2] = g_Rh[n*DD + tid + i2*256];
        rt[i2] = g_Rt[n*DD + tid + i2*256];
    }
    __syncthreads();
    const float* wh = g_w + (b*NE + hi)*KK*NM;
    const float* wt = g_w + (b*NE + ti)*KK*NM;
    for (int k = 0; k < KK; k++) {
        float whr[NM], wtr[NM];
        #pragma unroll
        for (int m = 0; m < NM; m++) {
            whr[m] = __ldg(&wh[k*NM + m]);
            wtr[m] = __ldg(&wt[k*NM + m]);
        }
        #pragma unroll
        for (int i2 = 0; i2 < 3; i2++) {
            int d = tid + i2*256;
            float ah = rh[i2], at2 = rt[i2];
            #pragma unroll
            for (int m = 0; m < NM; m++) {
                ah  += whr[m] * sT[m*DD + d];
                at2 += wtr[m] * sT[NM*DD + m*DD + d];
            }
            size_t o = (size_t)(n*KK + k)*DD + d;
            g_hs[o] = ftanh(ah);
            float tv = ftanh(at2);
            __half thi = __float2half_rn(tv);
            g_tshi[o] = thi;
            g_tslo[o] = __float2half_rn(tv - __half2float(thi));
        }
    }
}

// ---------------- K11: bilinear weights -> fp16 ----------------
__global__ void k_bhalf(const float* __restrict__ bil)
{
    size_t i4 = (size_t)blockIdx.x * 256 + threadIdx.x;
    const size_t N4 = (size_t)KK*DD*DD / 4;
    if (i4 >= N4) return;
    float4 v = ((const float4*)bil)[i4];
    __half2* ph = (__half2*)g_Bhi;
    ph[i4*2+0] = __floats2half2_rn(v.x, v.y);
    ph[i4*2+1] = __floats2half2_rn(v.z, v.w);
}

// ================= HMMA (mma.sync fp16) bilinear core =================
// 2 passes: (ts_hi + ts_lo) x B_hi. Block tile 128x128, Kstage = 64 fp16.
#define SW128(o) ((o) ^ (((o) >> 3) & 0x70))
#define TILE_BYTES 16384                   /* 128 rows x 128B */
#define SH_PITCH 132
#define SMEM_DYN (128*SH_PITCH*4 + 128*2*4 + 1024)

__device__ __forceinline__ void cp16(uint32_t dst, const void* src)
{
    asm volatile("cp.async.cg.shared.global [%0], [%1], 16;" :: "r"(dst), "l"(src));
}
__device__ __forceinline__ void ldm4(uint32_t* r, uint32_t addr)
{
    asm volatile("ldmatrix.sync.aligned.m8n8.x4.shared.b16 {%0,%1,%2,%3}, [%4];"
                 : "=r"(r[0]), "=r"(r[1]), "=r"(r[2]), "=r"(r[3]) : "r"(addr));
}
__device__ __forceinline__ void mma16816(float* c, const uint32_t* a, const uint32_t* b)
{
    asm volatile("mma.sync.aligned.m16n8k16.row.col.f32.f16.f16.f32 "
                 "{%0,%1,%2,%3}, {%4,%5,%6,%7}, {%8,%9}, {%0,%1,%2,%3};"
                 : "+f"(c[0]), "+f"(c[1]), "+f"(c[2]), "+f"(c[3])
                 : "r"(a[0]), "r"(a[1]), "r"(a[2]), "r"(a[3]), "r"(b[0]), "r"(b[1]));
}

__global__ __launch_bounds__(256) void k_bilinear_mma()
{
    extern __shared__ char dsm[];
    char* smem = (char*)((((uintptr_t)dsm) + 1023) & ~(uintptr_t)1023);
    uint32_t sbase = (uint32_t)__cvta_generic_to_shared(smem);

    const int k  = blockIdx.y;
    const int nt = blockIdx.x & 3;
    const int dt = blockIdx.x >> 2;        // 0..5
    const int n0 = nt * 128, d0 = dt * 128;
    const int tid = threadIdx.x;
    const int lane = tid & 31, wid = tid >> 5;
    const int wm = (wid & 3) * 32;         // warp m offset (pairs)
    const int wn = (wid >> 2) * 64;        // warp n offset (d)

    const size_t aoff = ((size_t)n0 * KK + k) * DD;
    const size_t boff = ((size_t)k * DD + d0) * DD;
    const __half* Aseg[2] = { g_tshi + aoff, g_tslo + aoff };
    const __half* Bbase   = g_Bhi + boff;

    float acc[2][8][4];
    #pragma unroll
    for (int mi = 0; mi < 2; mi++)
        #pragma unroll
        for (int ni = 0; ni < 8; ni++)
            #pragma unroll
            for (int j = 0; j < 4; j++) acc[mi][ni][j] = 0.f;

    // fill stage it (0..23) into buffer buf
    auto fill = [&](int it, int buf) {
        int seg = it / 12;
        int k0  = (it % 12) * 64;
        const __half* As = Aseg[seg];
        const __half* Bs = Bbase;
        uint32_t abase = sbase + buf*2*TILE_BYTES;
        uint32_t bbase = abase + TILE_BYTES;
        #pragma unroll
        for (int j = 0; j < 8; j++) {
            int c = tid + j*256;           // 0..2047
            if (c < 1024) {
                int r = c >> 3, q = c & 7;
                cp16(abase + SW128(r*128 + q*16), As + (size_t)r*(KK*DD) + k0 + q*8);
            } else {
                int c2 = c - 1024;
                int r = c2 >> 3, q = c2 & 7;
                cp16(bbase + SW128(r*128 + q*16), Bs + (size_t)r*DD + k0 + q*8);
            }
        }
    };

    fill(0, 0);
    asm volatile("cp.async.commit_group;");

    for (int i = 0; i < 24; i++) {
        if (i + 1 < 24) {
            fill(i + 1, (i + 1) & 1);
            asm volatile("cp.async.commit_group;");
            asm volatile("cp.async.wait_group 1;");
        } else {
            asm volatile("cp.async.wait_group 0;");
        }
        __syncthreads();

        uint32_t abase = sbase + (i & 1)*2*TILE_BYTES;
        uint32_t bbase = abase + TILE_BYTES;
        #pragma unroll
        for (int ks = 0; ks < 4; ks++) {
            uint32_t af[2][4];
            #pragma unroll
            for (int mi = 0; mi < 2; mi++) {
                int row = wm + mi*16 + ((lane >> 3) & 1)*8 + (lane & 7);
                int cb  = ks*32 + (lane >> 4)*16;
                ldm4(af[mi], abase + SW128(row*128 + cb));
            }
            uint32_t bf[8][2];
            #pragma unroll
            for (int q = 0; q < 4; q++) {
                uint32_t r[4];
                int nrow = wn + (2*q + (lane >> 4))*8 + (lane & 7);
                int cb   = ks*32 + ((lane >> 3) & 1)*16;
                ldm4(r, bbase + SW128(nrow*128 + cb));
                bf[2*q+0][0] = r[0]; bf[2*q+0][1] = r[1];
                bf[2*q+1][0] = r[2]; bf[2*q+1][1] = r[3];
            }
            #pragma unroll
            for (int mi = 0; mi < 2; mi++)
                #pragma unroll
                for (int ni = 0; ni < 8; ni++)
                    mma16816(acc[mi][ni], af[mi], bf[ni]);
        }
        __syncthreads();
    }

    // ---- epilogue: partial[n] = sum_d C[n][d]*hs[n][d] ----
    float* sH  = (float*)smem;                     // [128][SH_PITCH]
    float* red = (float*)(smem + 128*SH_PITCH*4);  // [128][2]
    for (int idx = tid; idx < 128*32; idx += 256) {
        int r = idx >> 5, c4 = idx & 31;
        float4 v = *(const float4*)(g_hs + ((size_t)(n0 + r)*KK + k)*DD + d0 + c4*4);
        *(float4*)&sH[r*SH_PITCH + c4*4] = v;
    }
    __syncthreads();

    float p[2][2] = {{0.f, 0.f}, {0.f, 0.f}};
    #pragma unroll
    for (int mi = 0; mi < 2; mi++) {
        int r0 = wm + mi*16 + (lane >> 2);
        #pragma unroll
        for (int ni = 0; ni < 8; ni++) {
            int cb = wn + ni*8 + (lane & 3)*2;
            p[mi][0] += acc[mi][ni][0]*sH[r0*SH_PITCH + cb]
                      + acc[mi][ni][1]*sH[r0*SH_PITCH + cb + 1];
            p[mi][1] += acc[mi][ni][2]*sH[(r0+8)*SH_PITCH + cb]
                      + acc[mi][ni][3]*sH[(r0+8)*SH_PITCH + cb + 1];
        }
    }
    #pragma unroll
    for (int mi = 0; mi < 2; mi++)
        #pragma unroll
        for (int h = 0; h < 2; h++) {
            p[mi][h] += __shfl_xor_sync(0xffffffffu, p[mi][h], 1);
            p[mi][h] += __shfl_xor_sync(0xffffffffu, p[mi][h], 2);
        }
    if ((lane & 3) == 0) {
        int nw = wid >> 2;
        int rr = lane >> 2;
        #pragma unroll
        for (int mi = 0; mi < 2; mi++) {
            red[(wm + mi*16 + rr)*2 + nw]     = p[mi][0];
            red[(wm + mi*16 + rr + 8)*2 + nw] = p[mi][1];
        }
    }
    __syncthreads();
    if (tid < 128)
        g_part[((size_t)dt*NP + n0 + tid)*KK + k] = red[tid*2] + red[tid*2+1];
}

// ---------------- K13: finalize ----------------
__global__ void k_final(const float* __restrict__ bilb, float* __restrict__ out)
{
    int idx = blockIdx.x*256 + threadIdx.x;
    if (idx >= NP*KK) return;
    int k = idx % KK;
    float s = bilb[k];
    #pragma unroll
    for (int t = 0; t < 6; t++) s += g_part[t*(NP*KK) + idx];
    out[idx] = s;
}

// ---------------- launch ----------------
extern "C" void kernel_launch(void* const* d_in, const int* in_sizes, int n_in,
                              void* d_out, int out_size)
{
    const float* seq      = (const float*)d_in[0];
    const float* att      = (const float*)d_in[1];
    const float* mask     = (const float*)d_in[2];
    const int*   mpos     = (const int*)  d_in[3];
    const int*   pairs    = (const int*)  d_in[4];
    const float* Wattn    = (const float*)d_in[5];
    const float* battn    = (const float*)d_in[6];
    const float* attn_net = (const float*)d_in[7];
    const float* Wlin     = (const float*)d_in[8];
    const float* blin     = (const float*)d_in[9];
    const float* Wseg     = (const float*)d_in[10];
    const float* bseg     = (const float*)d_in[11];
    const float* Whead    = (const float*)d_in[12];
    const float* bhead    = (const float*)d_in[13];
    const float* Wtail    = (const float*)d_in[14];
    const float* btail    = (const float*)d_in[15];
    const float* bil      = (const float*)d_in[16];
    const float* bilb     = (const float*)d_in[17];
    float* out = (float*)d_out;

    float *emb, *t1, *anT, *sc, *htss, *Th, *Tt, *Rh, *Rt;
    cudaGetSymbolAddress((void**)&emb,  g_emb);
    cudaGetSymbolAddress((void**)&t1,   g_t1);
    cudaGetSymbolAddress((void**)&anT,  g_anT);
    cudaGetSymbolAddress((void**)&sc,   g_sc);
    cudaGetSymbolAddress((void**)&htss, g_htss);
    cudaGetSymbolAddress((void**)&Th,   g_Th);
    cudaGetSymbolAddress((void**)&Tt,   g_Tt);
    cudaGetSymbolAddress((void**)&Rh,   g_Rh);
    cudaGetSymbolAddress((void**)&Rt,   g_Rt);

    cudaFuncSetAttribute(k_bilinear_mma, cudaFuncAttributeMaxDynamicSharedMemorySize, SMEM_DYN);

    // B weight fp16 convert (independent; longest prep) first
    {
        size_t n4 = (size_t)KK*DD*DD/4;
        k_bhalf<<<(unsigned)((n4 + 255)/256), 256>>>(bil);
    }
    k_antr<<<(RR*128 + 255)/256, 256>>>(attn_net);
    // 1. gather mention embeddings + entity attention rows
    k_gather<<<BBS*NE, 256>>>(seq, att, mask, mpos);
    // 2. t1 = tanh(emb @ Wattn + battn)
    sgemm64<<<dim3(RR/64, (BBS*NE*NM)/64), 256>>>(emb, DD, Wattn, RR, battn, t1, RR, DD, 1);
    // 3. scores = t1 @ anT  -> softmax over mentions
    sgemm64<<<dim3(2, (BBS*NE*NM)/64), 256>>>(t1, RR, anT, 128, nullptr, sc, 128, RR, 0);
    k_softmax<<<BBS*NE, 128>>>(mask);
    // 4/5. T_h / T_t merged
    sgemm64_dual<<<dim3(2*(DD/64), (BBS*NE*NM)/64), 256>>>(emb, DD, Whead, Wtail, DD,
                                                           nullptr, nullptr, Th, Tt, DD, DD);
    // 6. S3 = seq @ Wlin
    k_S3<<<BBS*LL, 128>>>(seq, Wlin);
    // 7. ht -> x
    k_htx<<<dim3(NE*NE, BBS), 256>>>(blin);
    // 8. conv + relu at pairs
    k_htss<<<NP, 256>>>(pairs, Wseg, bseg);
    // 9. Rh / Rt merged
    sgemm64_dual<<<dim3(2*(DD/64), NP/64), 256>>>(htss, FF, Whead + DD*DD, Wtail + DD*DD, DD,
                                                  bhead, btail, Rh, Rt, DD, FF);
    // 10. hs fp32 + ts fp16 split
    k_hsts<<<NP, 256>>>(pairs);
    // 11. HMMA bilinear: grid (24 tiles, 97 k), fp16 2-pass
    k_bilinear_mma<<<dim3(24, 97), 256, SMEM_DYN>>>();
    // 12. finalize
    k_final<<<(NP*KK + 255)/256, 256>>>(bilb, out);
}